// round 7
// baseline (speedup 1.0000x reference)
#include <cuda_runtime.h>

#define BATCH   64
#define NTOK    4096
#define CH      1024
#define KANCH   8
#define NSPLIT  16
#define TOK_PER (NTOK / NSPLIT)   // 256
#define C4      (CH / 4)          // 256 float4 per row

// Scratch (device globals — no allocation allowed)
__device__ float    g_partial[NSPLIT * BATCH * CH];  // 4 MB
__device__ float    g_desc[BATCH * CH];              // normalized descriptors
__device__ int      g_ids[BATCH];
__device__ float    g_sim[BATCH];                    // desc_b . anchor[ids[b]]
__device__ unsigned g_cnt[BATCH];                    // monotone arrival counters
                                                     // (old % 16 == 15 detects the
                                                     //  16th arrival of THIS replay,
                                                     //  so no reset needed)

// ---------------------------------------------------------------------------
// Fused kernel: streaming partial sums (HBM-bound, 1 GiB) + per-batch
// combiner. The 16th block to finish a batch combines its partials, computes
// the normalized descriptor, cosine sims and argmax — overlapped with the
// rest of the streaming work. Measured ~149-151us (DRAM ~87% = ceiling).
// ---------------------------------------------------------------------------
__global__ __launch_bounds__(256, 8) void k_main(const float* __restrict__ x,
                                                 const float* __restrict__ anchors,
                                                 float* __restrict__ out) {
    const int ns = blockIdx.x;
    const int b  = blockIdx.y;
    const int t  = threadIdx.x;  // 0..255 -> channels 4t..4t+3

    // ---- streaming phase ----
    {
        const float4* p = reinterpret_cast<const float4*>(x)
                        + (size_t)b * NTOK * C4
                        + (size_t)ns * TOK_PER * C4
                        + t;
        float4 acc = make_float4(0.f, 0.f, 0.f, 0.f);
#pragma unroll 8
        for (int n = 0; n < TOK_PER; ++n) {
            float4 v = __ldg(p);
            p += C4;
            acc.x += v.x; acc.y += v.y; acc.z += v.z; acc.w += v.w;
        }
        reinterpret_cast<float4*>(g_partial)[(size_t)(ns * BATCH + b) * C4 + t] = acc;
    }

    __threadfence();
    __syncthreads();
    __shared__ unsigned s_old;
    if (t == 0) s_old = atomicAdd(&g_cnt[b], 1u);
    __syncthreads();
    if ((s_old & 15u) != 15u) return;   // not the last arrival for this batch

    __threadfence();   // acquire: order peers' partial stores before our loads

    // ---- combiner phase (one block per batch, 63/64 overlapped) ----
    const int lane = t & 31;
    const int w    = t >> 5;

    float4 s = make_float4(0.f, 0.f, 0.f, 0.f);
#pragma unroll
    for (int nsi = 0; nsi < NSPLIT; ++nsi) {
        float4 v = __ldcg(reinterpret_cast<const float4*>(g_partial)
                          + (size_t)(nsi * BATCH + b) * C4 + t);
        s.x += v.x; s.y += v.y; s.z += v.z; s.w += v.w;
    }
    const float inv_n = 1.0f / (float)NTOK;
    s.x *= inv_n; s.y *= inv_n; s.z *= inv_n; s.w *= inv_n;

    __shared__ float warp_s[8];
    __shared__ float s_invnorm;
    float ss = s.x * s.x + s.y * s.y + s.z * s.z + s.w * s.w;
#pragma unroll
    for (int off = 16; off > 0; off >>= 1)
        ss += __shfl_xor_sync(0xffffffffu, ss, off);
    if (lane == 0) warp_s[w] = ss;
    __syncthreads();
    if (t == 0) {
        float tot = 0.f;
#pragma unroll
        for (int i = 0; i < 8; ++i) tot += warp_s[i];
        s_invnorm = 1.0f / fmaxf(sqrtf(tot), 1e-12f);
    }
    __syncthreads();

    const float invn = s_invnorm;
    float4 d = make_float4(s.x * invn, s.y * invn, s.z * invn, s.w * invn);
    reinterpret_cast<float4*>(g_desc)[(size_t)b * C4 + t] = d;

    float dot[KANCH];
#pragma unroll
    for (int k = 0; k < KANCH; ++k) {
        float4 a = __ldg(reinterpret_cast<const float4*>(anchors) + (size_t)k * C4 + t);
        dot[k] = d.x * a.x + d.y * a.y + d.z * a.z + d.w * a.w;
    }
#pragma unroll
    for (int off = 16; off > 0; off >>= 1) {
#pragma unroll
        for (int k = 0; k < KANCH; ++k)
            dot[k] += __shfl_xor_sync(0xffffffffu, dot[k], off);
    }
    __shared__ float wd[8][KANCH];
    if (lane == 0) {
#pragma unroll
        for (int k = 0; k < KANCH; ++k) wd[w][k] = dot[k];
    }
    __syncthreads();
    if (t == 0) {
        float simk[KANCH];
#pragma unroll
        for (int k = 0; k < KANCH; ++k) {
            float acc = 0.f;
#pragma unroll
            for (int i = 0; i < 8; ++i) acc += wd[i][k];
            simk[k] = acc;
        }
        // argmin(1 - sim) == first max of sim (strict > keeps first occurrence)
        int   best   = 0;
        float best_s = simk[0];
#pragma unroll
        for (int k = 1; k < KANCH; ++k)
            if (simk[k] > best_s) { best_s = simk[k]; best = k; }
        g_ids[b] = best;
        g_sim[b] = best_s;        // a0 . d for the EMA recursion
        out[b]   = (float)best;
    }
}

// ---------------------------------------------------------------------------
// k_post: EMA via scalar coefficient recursion.
// a_t = (m*a_{t-1} + im*d_t)/r_t with unit-norm d => a_t is a linear combo of
// a0 and the assigned descriptors. Only scalars are sequential:
//   p_t  = c0*(a0.d_t) + sum_i c_i*(d_i.d_t)     (Gram + sim)
//   r_t^2= m^2 + im^2 + 2*m*im*p_t               (in [0.64, 1.21])
//   c_i *= m/r_t ;  c_t = im/r_t ;  c0 *= m/r_t
// Phases: lists -> same-anchor Gram (32 warps, parallel) -> 8 scalar chains
// -> parallel reconstruction. No vector state in any sequential chain.
// ---------------------------------------------------------------------------
__global__ __launch_bounds__(1024) void k_post(const float* __restrict__ anchors,
                                               const float* __restrict__ counts,
                                               float* __restrict__ out) {
    __shared__ float s_G[BATCH][BATCH];     // 16 KB (same-anchor entries only)
    __shared__ int   s_list[KANCH][BATCH];  // 2 KB
    __shared__ int   s_len[KANCH];
    __shared__ float s_coef[KANCH][BATCH];  // 2 KB
    __shared__ float s_c0[KANCH];
    __shared__ float s_sim[BATCH];
    __shared__ int   s_ids[BATCH];

    const int t    = threadIdx.x;       // 0..1023
    const int lane = t & 31;
    const int w    = t >> 5;            // warp 0..31

    // Phase A: per-anchor sample lists (order preserved => same chain order)
    if (t < BATCH) { s_ids[t] = g_ids[t]; s_sim[t] = g_sim[t]; }
    __syncthreads();
    if (t < KANCH) {
        int n = 0;
        for (int b = 0; b < BATCH; ++b)
            if (s_ids[b] == t) s_list[t][n++] = b;
        s_len[t] = n;
    }
    __syncthreads();

    // Phase B: same-anchor Gram entries. All warps walk the same deterministic
    // (g,i,j) enumeration; warp w handles indices where (idx % 32 == w).
    {
        int idx = 0;
        for (int g = 0; g < KANCH; ++g) {
            const int L = s_len[g];
            for (int i = 1; i < L; ++i) {
                for (int j = 0; j < i; ++j) {
                    if ((idx & 31) == w) {
                        const int b1 = s_list[g][i];
                        const int b2 = s_list[g][j];
                        float acc = 0.f;
#pragma unroll
                        for (int k = 0; k < 8; ++k) {
                            float4 u = __ldg(reinterpret_cast<const float4*>(g_desc)
                                             + (size_t)b1 * C4 + k * 32 + lane);
                            float4 v = __ldg(reinterpret_cast<const float4*>(g_desc)
                                             + (size_t)b2 * C4 + k * 32 + lane);
                            acc += u.x * v.x + u.y * v.y + u.z * v.z + u.w * v.w;
                        }
#pragma unroll
                        for (int off = 16; off > 0; off >>= 1)
                            acc += __shfl_xor_sync(0xffffffffu, acc, off);
                        if (lane == 0) { s_G[b1][b2] = acc; s_G[b2][b1] = acc; }
                    }
                    idx++;
                }
            }
        }
    }
    __syncthreads();

    // Phase C: scalar coefficient recursion, one thread per anchor.
    if (t < KANCH) {
        const int g = t;
        const int L = s_len[g];
        float c     = counts[g];
        float c0    = 1.0f;
        for (int st = 0; st < L; ++st) {
            const int bt = s_list[g][st];
            const float m  = (c < 1.0f) ? 0.0f : 0.9f;
            const float im = 1.0f - m;
            // p = a_{st-1} . d_st
            float p = c0 * s_sim[bt];
            for (int i = 0; i < st; ++i)
                p += s_coef[g][i] * s_G[s_list[g][i]][bt];
            const float r2    = m * m + im * im + 2.0f * m * im * p;
            const float inv_r = 1.0f / fmaxf(sqrtf(r2), 1e-12f);
            const float sc    = m * inv_r;
            c0 *= sc;
            for (int i = 0; i < st; ++i) s_coef[g][i] *= sc;
            s_coef[g][st] = im * inv_r;
            c += 1.0f;
        }
        s_c0[g] = c0;
        out[BATCH + KANCH * CH + g] = c;   // new counts
    }
    __syncthreads();

    // Phase D: reconstruct anchors. Thread t owns channel t for all 8 anchors;
    // all loads are coalesced row reads, coefficients broadcast from shared.
    for (int g = 0; g < KANCH; ++g) {
        float acc = s_c0[g] * __ldg(anchors + (size_t)g * CH + t);
        const int L = s_len[g];
        for (int i = 0; i < L; ++i)
            acc += s_coef[g][i] * g_desc[(size_t)s_list[g][i] * CH + t];
        out[BATCH + g * CH + t] = acc;
    }
}

// ---------------------------------------------------------------------------
extern "C" void kernel_launch(void* const* d_in, const int* in_sizes, int n_in,
                              void* d_out, int out_size) {
    const float* prompt_tokens = (const float*)d_in[0];  // [64,4096,1024] f32
    const float* anchors       = (const float*)d_in[1];  // [8,1024] f32
    const float* counts        = (const float*)d_in[2];  // [8] f32
    float* out = (float*)d_out;  // [64 ids | 8192 anchors | 8 counts] f32

    dim3 grid1(NSPLIT, BATCH);
    k_main<<<grid1, 256>>>(prompt_tokens, anchors, out);
    k_post<<<1, 1024>>>(anchors, counts, out);
}

// round 9
// speedup vs baseline: 1.0965x; 1.0965x over previous
#include <cuda_runtime.h>

#define BATCH   64
#define NTOK    4096
#define CH      1024
#define KANCH   8
#define NSPLIT  16
#define TOK_PER (NTOK / NSPLIT)   // 256
#define C4      (CH / 4)          // 256 float4 per row

// Scratch (device globals — no allocation allowed)
__device__ float    g_partial[NSPLIT * BATCH * CH];  // 4 MB
__device__ float    g_desc[BATCH * CH];              // normalized descriptors
__device__ int      g_ids[BATCH];
__device__ float    g_sim[BATCH];                    // desc_b . anchor[ids[b]]
__device__ float    g_gram[BATCH * BATCH];           // desc_i . desc_j
__device__ unsigned g_cnt[BATCH];                    // monotone arrival counters
                                                     // (old % 16 == 15 detects the
                                                     //  16th arrival of THIS replay,
                                                     //  so no reset needed)

// ---------------------------------------------------------------------------
// Fused kernel: streaming partial sums (HBM-bound, 1 GiB) + per-batch
// combiner. The 16th block to finish a batch combines its partials, computes
// the normalized descriptor, cosine sims and argmax — overlapped with the
// rest of the streaming work. Measured ~149-151us (DRAM ~87% = ceiling).
// ---------------------------------------------------------------------------
__global__ __launch_bounds__(256, 8) void k_main(const float* __restrict__ x,
                                                 const float* __restrict__ anchors,
                                                 float* __restrict__ out) {
    const int ns = blockIdx.x;
    const int b  = blockIdx.y;
    const int t  = threadIdx.x;  // 0..255 -> channels 4t..4t+3

    // ---- streaming phase ----
    {
        const float4* p = reinterpret_cast<const float4*>(x)
                        + (size_t)b * NTOK * C4
                        + (size_t)ns * TOK_PER * C4
                        + t;
        float4 acc = make_float4(0.f, 0.f, 0.f, 0.f);
#pragma unroll 8
        for (int n = 0; n < TOK_PER; ++n) {
            float4 v = __ldg(p);
            p += C4;
            acc.x += v.x; acc.y += v.y; acc.z += v.z; acc.w += v.w;
        }
        reinterpret_cast<float4*>(g_partial)[(size_t)(ns * BATCH + b) * C4 + t] = acc;
    }

    __threadfence();
    __syncthreads();
    __shared__ unsigned s_old;
    if (t == 0) s_old = atomicAdd(&g_cnt[b], 1u);
    __syncthreads();
    if ((s_old & 15u) != 15u) return;   // not the last arrival for this batch

    __threadfence();   // acquire: order peers' partial stores before our loads

    // ---- combiner phase (one block per batch, 63/64 overlapped) ----
    const int lane = t & 31;
    const int w    = t >> 5;

    float4 s = make_float4(0.f, 0.f, 0.f, 0.f);
#pragma unroll
    for (int nsi = 0; nsi < NSPLIT; ++nsi) {
        float4 v = __ldcg(reinterpret_cast<const float4*>(g_partial)
                          + (size_t)(nsi * BATCH + b) * C4 + t);
        s.x += v.x; s.y += v.y; s.z += v.z; s.w += v.w;
    }
    const float inv_n = 1.0f / (float)NTOK;
    s.x *= inv_n; s.y *= inv_n; s.z *= inv_n; s.w *= inv_n;

    __shared__ float warp_s[8];
    __shared__ float s_invnorm;
    float ss = s.x * s.x + s.y * s.y + s.z * s.z + s.w * s.w;
#pragma unroll
    for (int off = 16; off > 0; off >>= 1)
        ss += __shfl_xor_sync(0xffffffffu, ss, off);
    if (lane == 0) warp_s[w] = ss;
    __syncthreads();
    if (t == 0) {
        float tot = 0.f;
#pragma unroll
        for (int i = 0; i < 8; ++i) tot += warp_s[i];
        s_invnorm = 1.0f / fmaxf(sqrtf(tot), 1e-12f);
    }
    __syncthreads();

    const float invn = s_invnorm;
    float4 d = make_float4(s.x * invn, s.y * invn, s.z * invn, s.w * invn);
    reinterpret_cast<float4*>(g_desc)[(size_t)b * C4 + t] = d;

    float dot[KANCH];
#pragma unroll
    for (int k = 0; k < KANCH; ++k) {
        float4 a = __ldg(reinterpret_cast<const float4*>(anchors) + (size_t)k * C4 + t);
        dot[k] = d.x * a.x + d.y * a.y + d.z * a.z + d.w * a.w;
    }
#pragma unroll
    for (int off = 16; off > 0; off >>= 1) {
#pragma unroll
        for (int k = 0; k < KANCH; ++k)
            dot[k] += __shfl_xor_sync(0xffffffffu, dot[k], off);
    }
    __shared__ float wd[8][KANCH];
    if (lane == 0) {
#pragma unroll
        for (int k = 0; k < KANCH; ++k) wd[w][k] = dot[k];
    }
    __syncthreads();
    if (t == 0) {
        float simk[KANCH];
#pragma unroll
        for (int k = 0; k < KANCH; ++k) {
            float acc = 0.f;
#pragma unroll
            for (int i = 0; i < 8; ++i) acc += wd[i][k];
            simk[k] = acc;
        }
        // argmin(1 - sim) == first max of sim (strict > keeps first occurrence)
        int   best   = 0;
        float best_s = simk[0];
#pragma unroll
        for (int k = 1; k < KANCH; ++k)
            if (simk[k] > best_s) { best_s = simk[k]; best = k; }
        g_ids[b] = best;
        g_sim[b] = best_s;        // a0 . d for the EMA recursion
        out[b]   = (float)best;
    }
}

// ---------------------------------------------------------------------------
// k_gram: full 64x64 descriptor Gram matrix. Block i computes row i: desc_i
// staged in smem, 8 warps x 8 columns each. 512 warps across the chip ->
// latency fully hidden; ~16 MB of L2 traffic total (~2us).
// ---------------------------------------------------------------------------
__global__ __launch_bounds__(256) void k_gram() {
    const int i    = blockIdx.x;
    const int t    = threadIdx.x;
    const int lane = t & 31;
    const int w    = t >> 5;

    __shared__ float4 sdesc[C4];   // desc_i, 4 KB
    sdesc[t] = reinterpret_cast<const float4*>(g_desc)[(size_t)i * C4 + t];
    __syncthreads();

    for (int j = w; j < BATCH; j += 8) {
        float acc = 0.f;
#pragma unroll
        for (int k = 0; k < 8; ++k) {
            float4 u = sdesc[k * 32 + lane];
            float4 v = __ldg(reinterpret_cast<const float4*>(g_desc)
                             + (size_t)j * C4 + k * 32 + lane);
            acc += u.x * v.x + u.y * v.y + u.z * v.z + u.w * v.w;
        }
#pragma unroll
        for (int off = 16; off > 0; off >>= 1)
            acc += __shfl_xor_sync(0xffffffffu, acc, off);
        if (lane == 0) g_gram[i * BATCH + j] = acc;
    }
}

// ---------------------------------------------------------------------------
// k_post: EMA via scalar coefficient recursion (math validated in R7,
// rel_err 3.8e-7).  a_t = (m*a_{t-1} + im*d_t)/r_t with unit-norm d =>
// a_t is a linear combo of a0 and assigned descriptors; only scalars are
// sequential:
//   p_t  = c0*(a0.d_t) + sum_i c_i*(d_i.d_t)
//   r_t^2= m^2 + im^2 + 2*m*im*p_t
//   c_i *= m/r_t ;  c_t = im/r_t ;  c0 *= m/r_t
// Phase C is warp-per-anchor (lane-parallel dot + rescale, shfl reduce).
// ---------------------------------------------------------------------------
__global__ __launch_bounds__(1024) void k_post(const float* __restrict__ anchors,
                                               const float* __restrict__ counts,
                                               float* __restrict__ out) {
    __shared__ float s_G[BATCH * BATCH];    // 16 KB
    __shared__ int   s_list[KANCH][BATCH];
    __shared__ int   s_len[KANCH];
    __shared__ float s_coef[KANCH][BATCH];
    __shared__ float s_c0[KANCH];
    __shared__ float s_sim[BATCH];
    __shared__ int   s_ids[BATCH];

    const int t    = threadIdx.x;       // 0..1023
    const int lane = t & 31;
    const int w    = t >> 5;            // warp 0..31

    // Phase A: load Gram + ids/sims, build per-anchor lists (order preserved).
    for (int idx = t; idx < BATCH * BATCH; idx += 1024)
        s_G[idx] = g_gram[idx];
    if (t < BATCH) { s_ids[t] = g_ids[t]; s_sim[t] = g_sim[t]; }
    __syncthreads();
    if (t < KANCH) {
        int n = 0;
        for (int b = 0; b < BATCH; ++b)
            if (s_ids[b] == t) s_list[t][n++] = b;
        s_len[t] = n;
    }
    __syncthreads();

    // Phase C: warp-per-anchor scalar recursion (warps 0..7).
    if (w < KANCH) {
        const int g = w;
        const int L = s_len[g];
        float c  = __ldg(counts + g);   // replicated per lane (deterministic)
        float c0 = 1.0f;
        for (int st = 0; st < L; ++st) {
            const int bt = s_list[g][st];
            const float m  = (c < 1.0f) ? 0.0f : 0.9f;
            const float im = 1.0f - m;

            float part = 0.f;
            for (int i = lane; i < st; i += 32)
                part += s_coef[g][i] * s_G[s_list[g][i] * BATCH + bt];
#pragma unroll
            for (int off = 16; off > 0; off >>= 1)
                part += __shfl_xor_sync(0xffffffffu, part, off);

            const float p     = c0 * s_sim[bt] + part;
            const float r2    = m * m + im * im + 2.0f * m * im * p;
            const float inv_r = 1.0f / fmaxf(sqrtf(r2), 1e-12f);
            const float sc    = m * inv_r;

            c0 *= sc;
            for (int i = lane; i < st; i += 32) s_coef[g][i] *= sc;
            if (lane == 0) s_coef[g][st] = im * inv_r;
            c += 1.0f;
            __syncwarp();
        }
        if (lane == 0) {
            s_c0[g] = c0;
            out[BATCH + KANCH * CH + g] = c;   // new counts
        }
    }
    __syncthreads();

    // Phase D: reconstruct anchors. Thread t owns channel t for all 8 anchors;
    // coalesced row reads, coefficients broadcast from shared.
    for (int g = 0; g < KANCH; ++g) {
        float acc = s_c0[g] * __ldg(anchors + (size_t)g * CH + t);
        const int L = s_len[g];
        for (int i = 0; i < L; ++i)
            acc += s_coef[g][i] * g_desc[(size_t)s_list[g][i] * CH + t];
        out[BATCH + g * CH + t] = acc;
    }
}

// ---------------------------------------------------------------------------
extern "C" void kernel_launch(void* const* d_in, const int* in_sizes, int n_in,
                              void* d_out, int out_size) {
    const float* prompt_tokens = (const float*)d_in[0];  // [64,4096,1024] f32
    const float* anchors       = (const float*)d_in[1];  // [8,1024] f32
    const float* counts        = (const float*)d_in[2];  // [8] f32
    float* out = (float*)d_out;  // [64 ids | 8192 anchors | 8 counts] f32

    dim3 grid1(NSPLIT, BATCH);
    k_main<<<grid1, 256>>>(prompt_tokens, anchors, out);
    k_gram<<<BATCH, 256>>>();
    k_post<<<1, 1024>>>(anchors, counts, out);
}

// round 10
// speedup vs baseline: 1.1088x; 1.0111x over previous
#include <cuda_runtime.h>

#define BATCH   64
#define NTOK    4096
#define CH      1024
#define KANCH   8
#define NSPLIT  16
#define TOK_PER (NTOK / NSPLIT)   // 256
#define C4      (CH / 4)          // 256 float4 per row

// Scratch (device globals — no allocation allowed)
__device__ float    g_partial[NSPLIT * BATCH * CH];  // 4 MB
__device__ float    g_desc[BATCH * CH];              // normalized descriptors
__device__ int      g_ids[BATCH];
__device__ float    g_sim[BATCH];                    // desc_b . anchor[ids[b]]
__device__ float    g_gram[BATCH * BATCH];           // desc_i . desc_j
__device__ unsigned g_cnt[BATCH];                    // monotone arrival counters
                                                     // (old % 16 == 15 detects the
                                                     //  16th arrival of THIS replay,
                                                     //  so no reset needed)

// ---------------------------------------------------------------------------
// Fused kernel: streaming partial sums (HBM-bound, 1 GiB) + per-batch
// combiner. The 16th block to finish a batch combines its partials, computes
// the normalized descriptor, cosine sims and argmax — overlapped with the
// rest of the streaming work. ~150us at ~87% DRAM (practical ceiling).
// ---------------------------------------------------------------------------
__global__ __launch_bounds__(256, 8) void k_main(const float* __restrict__ x,
                                                 const float* __restrict__ anchors,
                                                 float* __restrict__ out) {
    const int ns = blockIdx.x;
    const int b  = blockIdx.y;
    const int t  = threadIdx.x;  // 0..255 -> channels 4t..4t+3

    // ---- streaming phase ----
    {
        const float4* p = reinterpret_cast<const float4*>(x)
                        + (size_t)b * NTOK * C4
                        + (size_t)ns * TOK_PER * C4
                        + t;
        float4 acc = make_float4(0.f, 0.f, 0.f, 0.f);
#pragma unroll 8
        for (int n = 0; n < TOK_PER; ++n) {
            float4 v = __ldg(p);
            p += C4;
            acc.x += v.x; acc.y += v.y; acc.z += v.z; acc.w += v.w;
        }
        reinterpret_cast<float4*>(g_partial)[(size_t)(ns * BATCH + b) * C4 + t] = acc;
    }

    __threadfence();
    __syncthreads();
    __shared__ unsigned s_old;
    if (t == 0) s_old = atomicAdd(&g_cnt[b], 1u);
    __syncthreads();
    if ((s_old & 15u) != 15u) return;   // not the last arrival for this batch

    __threadfence();   // acquire: order peers' partial stores before our loads

    // ---- combiner phase (one block per batch, 63/64 overlapped) ----
    const int lane = t & 31;
    const int w    = t >> 5;

    float4 s = make_float4(0.f, 0.f, 0.f, 0.f);
#pragma unroll
    for (int nsi = 0; nsi < NSPLIT; ++nsi) {
        float4 v = __ldcg(reinterpret_cast<const float4*>(g_partial)
                          + (size_t)(nsi * BATCH + b) * C4 + t);
        s.x += v.x; s.y += v.y; s.z += v.z; s.w += v.w;
    }
    const float inv_n = 1.0f / (float)NTOK;
    s.x *= inv_n; s.y *= inv_n; s.z *= inv_n; s.w *= inv_n;

    __shared__ float warp_s[8];
    __shared__ float s_invnorm;
    float ss = s.x * s.x + s.y * s.y + s.z * s.z + s.w * s.w;
#pragma unroll
    for (int off = 16; off > 0; off >>= 1)
        ss += __shfl_xor_sync(0xffffffffu, ss, off);
    if (lane == 0) warp_s[w] = ss;
    __syncthreads();
    if (t == 0) {
        float tot = 0.f;
#pragma unroll
        for (int i = 0; i < 8; ++i) tot += warp_s[i];
        s_invnorm = 1.0f / fmaxf(sqrtf(tot), 1e-12f);
    }
    __syncthreads();

    const float invn = s_invnorm;
    float4 d = make_float4(s.x * invn, s.y * invn, s.z * invn, s.w * invn);
    reinterpret_cast<float4*>(g_desc)[(size_t)b * C4 + t] = d;

    float dot[KANCH];
#pragma unroll
    for (int k = 0; k < KANCH; ++k) {
        float4 a = __ldg(reinterpret_cast<const float4*>(anchors) + (size_t)k * C4 + t);
        dot[k] = d.x * a.x + d.y * a.y + d.z * a.z + d.w * a.w;
    }
#pragma unroll
    for (int off = 16; off > 0; off >>= 1) {
#pragma unroll
        for (int k = 0; k < KANCH; ++k)
            dot[k] += __shfl_xor_sync(0xffffffffu, dot[k], off);
    }
    __shared__ float wd[8][KANCH];
    if (lane == 0) {
#pragma unroll
        for (int k = 0; k < KANCH; ++k) wd[w][k] = dot[k];
    }
    __syncthreads();
    if (t == 0) {
        float simk[KANCH];
#pragma unroll
        for (int k = 0; k < KANCH; ++k) {
            float acc = 0.f;
#pragma unroll
            for (int i = 0; i < 8; ++i) acc += wd[i][k];
            simk[k] = acc;
        }
        // argmin(1 - sim) == first max of sim (strict > keeps first occurrence)
        int   best   = 0;
        float best_s = simk[0];
#pragma unroll
        for (int k = 1; k < KANCH; ++k)
            if (simk[k] > best_s) { best_s = simk[k]; best = k; }
        g_ids[b] = best;
        g_sim[b] = best_s;        // a0 . d for the EMA recursion
        out[b]   = (float)best;
    }
}

// ---------------------------------------------------------------------------
// k_gram: full 64x64 descriptor Gram matrix. Block i computes row i: desc_i
// staged in smem, 8 warps x 8 columns each (2 columns per step -> loads for
// both dots issue before either reduction). 512 warps across the chip.
// ---------------------------------------------------------------------------
__global__ __launch_bounds__(256) void k_gram() {
    const int i    = blockIdx.x;
    const int t    = threadIdx.x;
    const int lane = t & 31;
    const int w    = t >> 5;

    __shared__ float4 sdesc[C4];   // desc_i, 4 KB
    sdesc[t] = reinterpret_cast<const float4*>(g_desc)[(size_t)i * C4 + t];
    __syncthreads();

#pragma unroll
    for (int jj = 0; jj < 4; ++jj) {
        const int j0 = w + (2 * jj)     * 8;
        const int j1 = w + (2 * jj + 1) * 8;
        float acc0 = 0.f, acc1 = 0.f;
#pragma unroll
        for (int k = 0; k < 8; ++k) {
            float4 u  = sdesc[k * 32 + lane];
            float4 v0 = __ldg(reinterpret_cast<const float4*>(g_desc)
                              + (size_t)j0 * C4 + k * 32 + lane);
            float4 v1 = __ldg(reinterpret_cast<const float4*>(g_desc)
                              + (size_t)j1 * C4 + k * 32 + lane);
            acc0 += u.x * v0.x + u.y * v0.y + u.z * v0.z + u.w * v0.w;
            acc1 += u.x * v1.x + u.y * v1.y + u.z * v1.z + u.w * v1.w;
        }
#pragma unroll
        for (int off = 16; off > 0; off >>= 1) {
            acc0 += __shfl_xor_sync(0xffffffffu, acc0, off);
            acc1 += __shfl_xor_sync(0xffffffffu, acc1, off);
        }
        if (lane == 0) {
            g_gram[i * BATCH + j0] = acc0;
            g_gram[i * BATCH + j1] = acc1;
        }
    }
}

// ---------------------------------------------------------------------------
// k_post: EMA via scalar coefficient recursion (math validated: rel_err
// 3.8e-7). a_t = (m*a_{t-1} + im*d_t)/r_t with unit-norm d => a_t is a
// linear combo of a0 and assigned descriptors; only scalars are sequential:
//   p_t  = c0*(a0.d_t) + sum_i c_i*(d_i.d_t)
//   r_t^2= m^2 + im^2 + 2*m*im*p_t            (in [0.64, 1.21] -> rsqrtf ok)
//   c_i *= m/r_t ;  c_t = im/r_t ;  c0 *= m/r_t
// Phase C: warp-per-anchor. Phase D: 4-wide load batching (R9's 10us Phase D
// was MLP=1 on the acc chain).
// ---------------------------------------------------------------------------
__global__ __launch_bounds__(1024) void k_post(const float* __restrict__ anchors,
                                               const float* __restrict__ counts,
                                               float* __restrict__ out) {
    __shared__ float s_G[BATCH * BATCH];    // 16 KB
    __shared__ int   s_list[KANCH][BATCH];
    __shared__ int   s_len[KANCH];
    __shared__ float s_coef[KANCH][BATCH];
    __shared__ float s_c0[KANCH];
    __shared__ float s_sim[BATCH];
    __shared__ int   s_ids[BATCH];

    const int t    = threadIdx.x;       // 0..1023
    const int lane = t & 31;
    const int w    = t >> 5;            // warp 0..31

    // Phase A: load Gram (float4-batched) + ids/sims, build per-anchor lists.
    for (int idx = t; idx < BATCH * BATCH / 4; idx += 1024)
        reinterpret_cast<float4*>(s_G)[idx] =
            __ldg(reinterpret_cast<const float4*>(g_gram) + idx);
    if (t < BATCH) { s_ids[t] = g_ids[t]; s_sim[t] = g_sim[t]; }
    __syncthreads();
    if (t < KANCH) {
        int n = 0;
        for (int b = 0; b < BATCH; ++b)
            if (s_ids[b] == t) s_list[t][n++] = b;
        s_len[t] = n;
    }
    __syncthreads();

    // Phase C: warp-per-anchor scalar recursion (warps 0..7).
    if (w < KANCH) {
        const int g = w;
        const int L = s_len[g];
        float c  = __ldg(counts + g);
        float c0 = 1.0f;
        for (int st = 0; st < L; ++st) {
            const int bt = s_list[g][st];
            const float m  = (c < 1.0f) ? 0.0f : 0.9f;
            const float im = 1.0f - m;

            float part = 0.f;
            for (int i = lane; i < st; i += 32)
                part += s_coef[g][i] * s_G[s_list[g][i] * BATCH + bt];
#pragma unroll
            for (int off = 16; off > 0; off >>= 1)
                part += __shfl_xor_sync(0xffffffffu, part, off);

            const float p     = c0 * s_sim[bt] + part;
            const float r2    = m * m + im * im + 2.0f * m * im * p;
            const float inv_r = rsqrtf(r2);     // r2 in [0.64,1.21], eps never binds
            const float sc    = m * inv_r;

            c0 *= sc;
            for (int i = lane; i < st; i += 32) s_coef[g][i] *= sc;
            if (lane == 0) s_coef[g][st] = im * inv_r;
            c += 1.0f;
            __syncwarp();
        }
        if (lane == 0) {
            s_c0[g] = c0;
            out[BATCH + KANCH * CH + g] = c;   // new counts
        }
    }
    __syncthreads();

    // Phase D: reconstruct anchors. Thread t owns channel t. 4-wide manual
    // batching: stage 4 descriptor loads (address-independent of acc) before
    // consuming them -> MLP 4 instead of 1.
    for (int g = 0; g < KANCH; ++g) {
        float acc = s_c0[g] * __ldg(anchors + (size_t)g * CH + t);
        const int L = s_len[g];
        int i = 0;
        for (; i + 4 <= L; i += 4) {
            const int b0 = s_list[g][i],     b1 = s_list[g][i + 1];
            const int b2 = s_list[g][i + 2], b3 = s_list[g][i + 3];
            const float v0 = g_desc[(size_t)b0 * CH + t];
            const float v1 = g_desc[(size_t)b1 * CH + t];
            const float v2 = g_desc[(size_t)b2 * CH + t];
            const float v3 = g_desc[(size_t)b3 * CH + t];
            acc += s_coef[g][i]     * v0;
            acc += s_coef[g][i + 1] * v1;
            acc += s_coef[g][i + 2] * v2;
            acc += s_coef[g][i + 3] * v3;
        }
        for (; i < L; ++i)
            acc += s_coef[g][i] * g_desc[(size_t)s_list[g][i] * CH + t];
        out[BATCH + g * CH + t] = acc;
    }
}

// ---------------------------------------------------------------------------
extern "C" void kernel_launch(void* const* d_in, const int* in_sizes, int n_in,
                              void* d_out, int out_size) {
    const float* prompt_tokens = (const float*)d_in[0];  // [64,4096,1024] f32
    const float* anchors       = (const float*)d_in[1];  // [8,1024] f32
    const float* counts        = (const float*)d_in[2];  // [8] f32
    float* out = (float*)d_out;  // [64 ids | 8192 anchors | 8 counts] f32

    dim3 grid1(NSPLIT, BATCH);
    k_main<<<grid1, 256>>>(prompt_tokens, anchors, out);
    k_gram<<<BATCH, 256>>>();
    k_post<<<1, 1024>>>(anchors, counts, out);
}